// round 1
// baseline (speedup 1.0000x reference)
#include <cuda_runtime.h>

// Problem constants (B=2, H=16, N=2048, D=64)
#define THREADS 256
#define TQ      16          // query rows per CTA
#define TK      256         // key tile rows
#define DH      64          // head dim
#define NSEQ    2048
#define LDK     (DH + 4)    // padded smem row stride (floats)
#define NEG_INF_F (-1000000000.0f)

// dynamic smem layout:
//   float S [TQ][NSEQ]   : score / prob tile        (131072 B)
//   float Ks[TK][LDK]    : K tile (reused for V)    ( 69632 B)
//   float Qs[TQ][LDK]    : Q tile, pre-scaled 1/8   (  4352 B)
//   int   mks[NSEQ]      : key-side mask            (  8192 B)
//   int   mqs[TQ]        : query-side mask          (    64 B)
#define SMEM_BYTES ((TQ*NSEQ + TK*LDK + TQ*LDK) * 4 + NSEQ * 4 + TQ * 4)

__global__ __launch_bounds__(THREADS, 1)
void attn_fused_kernel(const float* __restrict__ gq,
                       const float* __restrict__ gk,
                       const float* __restrict__ gv,
                       const int*   __restrict__ gmask,
                       float* __restrict__ gout,
                       float* __restrict__ gattn)
{
    extern __shared__ float sm[];
    float* S   = sm;                          // TQ * NSEQ
    float* Ks  = S  + TQ * NSEQ;              // TK * LDK
    float* Qs  = Ks + TK * LDK;               // TQ * LDK
    int*   mks = (int*)(Qs + TQ * LDK);       // NSEQ
    int*   mqs = mks + NSEQ;                  // TQ

    const int tid = threadIdx.x;
    const int bh  = blockIdx.y;               // 0..31 (b*16 + h)
    const int b   = bh >> 4;
    const int q0  = blockIdx.x * TQ;

    const float* qbase = gq + ((size_t)bh * NSEQ + q0) * DH;
    const float* kbase = gk + (size_t)bh * NSEQ * DH;
    const float* vbase = gv + (size_t)bh * NSEQ * DH;

    // ---- mask + Q tile load (Q pre-scaled by 1/TEMPERATURE = 0.125, exact) ----
    for (int i = tid; i < NSEQ; i += THREADS) mks[i] = gmask[b * NSEQ + i];
    if (tid < TQ) mqs[tid] = gmask[b * NSEQ + q0 + tid];
    {
        int r = tid >> 4;
        int d = (tid & 15) << 2;
        float4 qv = *(const float4*)(qbase + r * DH + d);
        qv.x *= 0.125f; qv.y *= 0.125f; qv.z *= 0.125f; qv.w *= 0.125f;
        *(float4*)&Qs[r * LDK + d] = qv;
    }

    // ---- S = (Q/8) K^T with symmetric mask -> NEG_INF ----
    const int r0 = (tid >> 6) << 2;   // 0,4,8,12
    const int c0 = (tid & 63) << 2;   // 0..252 step 4

    for (int kt = 0; kt < NSEQ; kt += TK) {
        __syncthreads();
        #pragma unroll
        for (int i = 0; i < (TK * DH / 4) / THREADS; i++) {   // 16 float4 each
            int idx = tid + i * THREADS;
            int row = idx >> 4;
            int d   = (idx & 15) << 2;
            *(float4*)&Ks[row * LDK + d] =
                *(const float4*)(kbase + (size_t)(kt + row) * DH + d);
        }
        __syncthreads();

        float acc[4][4] = {};
        #pragma unroll 4
        for (int d = 0; d < DH; d += 4) {
            float4 qa[4], kb[4];
            #pragma unroll
            for (int i = 0; i < 4; i++) qa[i] = *(const float4*)&Qs[(r0 + i) * LDK + d];
            #pragma unroll
            for (int j = 0; j < 4; j++) kb[j] = *(const float4*)&Ks[(c0 + j) * LDK + d];
            #pragma unroll
            for (int i = 0; i < 4; i++)
                #pragma unroll
                for (int j = 0; j < 4; j++)
                    acc[i][j] += qa[i].x * kb[j].x + qa[i].y * kb[j].y
                               + qa[i].z * kb[j].z + qa[i].w * kb[j].w;
        }

        int mk0 = mks[kt + c0 + 0], mk1 = mks[kt + c0 + 1];
        int mk2 = mks[kt + c0 + 2], mk3 = mks[kt + c0 + 3];
        #pragma unroll
        for (int i = 0; i < 4; i++) {
            int mq = mqs[r0 + i];
            float4 sv;
            sv.x = (mq | mk0) ? NEG_INF_F : acc[i][0];
            sv.y = (mq | mk1) ? NEG_INF_F : acc[i][1];
            sv.z = (mq | mk2) ? NEG_INF_F : acc[i][2];
            sv.w = (mq | mk3) ? NEG_INF_F : acc[i][3];
            *(float4*)&S[(size_t)(r0 + i) * NSEQ + kt + c0] = sv;
        }
    }

    __syncthreads();

    // ---- row softmax in smem; stream normalized probs to gattn ----
    const int warp = tid >> 5;
    const int lane = tid & 31;
    for (int r = warp; r < TQ; r += 8) {
        float* row = &S[(size_t)r * NSEQ];
        float m = NEG_INF_F;
        for (int i = lane; i < NSEQ; i += 32) m = fmaxf(m, row[i]);
        #pragma unroll
        for (int o = 16; o > 0; o >>= 1) m = fmaxf(m, __shfl_xor_sync(0xffffffffu, m, o));
        float l = 0.0f;
        for (int i = lane; i < NSEQ; i += 32) {
            float e = __expf(row[i] - m);   // masked row: all exp(0)=1 -> uniform 1/N (matches ref)
            row[i] = e;
            l += e;
        }
        #pragma unroll
        for (int o = 16; o > 0; o >>= 1) l += __shfl_xor_sync(0xffffffffu, l, o);
        float inv = 1.0f / l;
        float* arow = gattn + ((size_t)bh * NSEQ + q0 + r) * NSEQ;
        for (int i = lane; i < NSEQ; i += 32) {
            float p = row[i] * inv;
            row[i]  = p;        // keep prob in smem for PV
            arow[i] = p;        // coalesced attn write
        }
    }

    // ---- O = P V : per-thread 1q x 8d, k-range split across block halves ----
    const int half = tid >> 7;            // 0 or 1
    const int u    = tid & 127;
    const int rr   = u >> 3;              // 0..15
    const int cc   = (u & 7) << 3;        // 0,8,...,56
    float o[8] = {0,0,0,0,0,0,0,0};

    for (int kt = 0; kt < NSEQ; kt += TK) {
        __syncthreads();
        #pragma unroll
        for (int i = 0; i < (TK * DH / 4) / THREADS; i++) {   // V tile into Ks
            int idx = tid + i * THREADS;
            int row = idx >> 4;
            int d   = (idx & 15) << 2;
            *(float4*)&Ks[row * LDK + d] =
                *(const float4*)(vbase + (size_t)(kt + row) * DH + d);
        }
        __syncthreads();

        const int kbeg = half * (TK / 2);
        #pragma unroll 8
        for (int kk = 0; kk < TK / 2; kk += 4) {
            int krow = kbeg + kk;
            float4 p4 = *(const float4*)&S[(size_t)rr * NSEQ + kt + krow];
            #pragma unroll
            for (int t = 0; t < 4; t++) {
                float pt = (t == 0) ? p4.x : (t == 1) ? p4.y : (t == 2) ? p4.z : p4.w;
                const float* vrow = &Ks[(krow + t) * LDK + cc];
                float4 va = *(const float4*)vrow;
                float4 vb = *(const float4*)(vrow + 4);
                o[0] += pt * va.x; o[1] += pt * va.y; o[2] += pt * va.z; o[3] += pt * va.w;
                o[4] += pt * vb.x; o[5] += pt * vb.y; o[6] += pt * vb.z; o[7] += pt * vb.w;
            }
        }
    }

    // combine the two k-halves via smem scratch (S is free now)
    __syncthreads();
    float* scratch = S;
    if (half == 1) {
        #pragma unroll
        for (int j = 0; j < 8; j++) scratch[u * 8 + j] = o[j];
    }
    __syncthreads();
    if (half == 0) {
        float* op = gout + ((size_t)bh * NSEQ + q0 + rr) * DH + cc;
        #pragma unroll
        for (int j = 0; j < 8; j++) op[j] = o[j] + scratch[u * 8 + j];
    }
}

extern "C" void kernel_launch(void* const* d_in, const int* in_sizes, int n_in,
                              void* d_out, int out_size)
{
    const float* q    = (const float*)d_in[0];
    const float* k    = (const float*)d_in[1];
    const float* v    = (const float*)d_in[2];
    const int*   mask = (const int*)d_in[3];

    float* out  = (float*)d_out;
    float* attn = out + (size_t)2 * 16 * 2048 * 64;   // output first, then attn

    static_assert(SMEM_BYTES <= 232448, "smem over sm_103a limit");
    cudaFuncSetAttribute(attn_fused_kernel,
                         cudaFuncAttributeMaxDynamicSharedMemorySize, SMEM_BYTES);

    dim3 grid(NSEQ / TQ, 32);   // 128 q-tiles x 32 (b*h); x-fastest keeps K/V hot in L2
    attn_fused_kernel<<<grid, THREADS, SMEM_BYTES>>>(q, k, v, mask, out, attn);
}